// round 13
// baseline (speedup 1.0000x reference)
#include <cuda_runtime.h>

// ---------------- problem constants (fixed shapes) ----------------
#define B_    4
#define D_    118
#define H_    32              // == warp size: lane <-> h
#define W_    88
#define C_    80
#define NX_   360
#define NY_   360
#define XY_   (NX_ * NY_)     // 129600
#define NCOLB (D_ * W_)       // 10,384 columns per batch (divisible by 4)
#define NCOL  (B_ * NCOLB)    // 41,536 ray columns
#define WPB_  4               // columns (warps) per block

// ---------------- kernel 1: zero all of d_out (poisoned 0xAA) --------------
__global__ void zero_out_kernel(float4* __restrict__ o) {
    unsigned i = blockIdx.x * blockDim.x + threadIdx.x;
    o[i] = make_float4(0.f, 0.f, 0.f, 0.f);   // grid sized exactly: no guard
}

// ---------------- kernel 2: warp-per-column scatter, block-wide commit -----
// Structural fact (validated R5-R12): combine[0][1] == combine[1][1] == 0
// exactly in fp32, so gx,gy are identical across the 32 h's of a (b,d,w)
// column; only the cz==0 test varies with h. Phase 1: each of the 4 warps
// computes its column's mask/voxel (lane == h) with ballot + uniformity
// fallback. Phase 2: the proven register-accumulate loop (warp-uniform mask
// -> scalar branch skips failing h's), results staged in smem. Phase 3:
// channel-major commit across the block's 4 adjacent-w columns — 4
// consecutive lanes share channel c and hit 4 neighboring q's, collapsing
// atomic sectors (R12's proven win). 128-thread blocks quantize to 12
// blocks/SM (48 warps, 75% occ) and double the grid for a smoother drain.
__global__ void __launch_bounds__(128)
scatter_kernel(const float* __restrict__ x, const float* __restrict__ frustum,
               float* __restrict__ out,
               const float* __restrict__ rots,
               const float* __restrict__ trans,
               const float* __restrict__ intrins) {
    __shared__ float    s_cmb[9];
    __shared__ float    s_tr[3];
    __shared__ float    s_acc[WPB_][C_];
    __shared__ unsigned s_mask[WPB_];
    __shared__ unsigned s_q[WPB_];

    unsigned tid  = threadIdx.x;
    unsigned lane = tid & 31u;                    // lane == h
    unsigned wid  = tid >> 5;
    unsigned col  = blockIdx.x * WPB_ + wid;      // one column per warp
    unsigned w = col % W_;
    unsigned t = col / W_;
    unsigned d = t % D_;
    unsigned b = t / D_;                          // uniform across the block

    // --- per-block setup: combine = rots[b] @ inv(intrins[b]) (dbl adjugate)
    if (tid == 0) {
        const float* K = intrins + b * 9;
        double a00 = K[0], a01 = K[1], a02 = K[2];
        double a10 = K[3], a11 = K[4], a12 = K[5];
        double a20 = K[6], a21 = K[7], a22 = K[8];
        double det = a00 * (a11 * a22 - a12 * a21)
                   - a01 * (a10 * a22 - a12 * a20)
                   + a02 * (a10 * a21 - a11 * a20);
        double id = 1.0 / det;
        float inv[9];
        inv[0] = (float)(( a11 * a22 - a12 * a21) * id);
        inv[1] = (float)((-(a01 * a22 - a02 * a21)) * id);
        inv[2] = (float)(( a01 * a12 - a02 * a11) * id);
        inv[3] = (float)((-(a10 * a22 - a12 * a20)) * id);
        inv[4] = (float)(( a00 * a22 - a02 * a20) * id);
        inv[5] = (float)((-(a00 * a12 - a02 * a10)) * id);
        inv[6] = (float)(( a10 * a21 - a11 * a20) * id);
        inv[7] = (float)((-(a00 * a21 - a01 * a20)) * id);
        inv[8] = (float)(( a00 * a11 - a01 * a10) * id);
        const float* R = rots + b * 9;
        #pragma unroll
        for (int i = 0; i < 3; i++)
            #pragma unroll
            for (int j = 0; j < 3; j++)
                s_cmb[i * 3 + j] = R[i * 3 + 0] * inv[0 * 3 + j]
                                 + R[i * 3 + 1] * inv[1 * 3 + j]
                                 + R[i * 3 + 2] * inv[2 * 3 + j];
        s_tr[0] = trans[b * 3 + 0];
        s_tr[1] = trans[b * 3 + 1];
        s_tr[2] = trans[b * 3 + 2];
    }
    __syncthreads();

    // --------------- phase 1: mask + voxel for this warp's column -----------
    // frustum (D,H,W,3): [...,0]=u (w only), [...,1]=v (h only), [...,2]=depth
    const float* fr = frustum + ((d * H_ + lane) * W_ + w) * 3u;
    float fu = fr[0];     // uniform across lanes
    float fv = fr[1];     // per-lane (h)
    float fd = fr[2];     // uniform across lanes
    float p0 = fu * fd, p1 = fv * fd, p2 = fd;

    float gx = s_cmb[0] * p0 + s_cmb[1] * p1 + s_cmb[2] * p2 + s_tr[0];
    float gy = s_cmb[3] * p0 + s_cmb[4] * p1 + s_cmb[5] * p2 + s_tr[1];
    float gz = s_cmb[6] * p0 + s_cmb[7] * p1 + s_cmb[8] * p2 + s_tr[2];

    // matches ((geom - BX_LO)/DX).astype(int32): trunc toward zero,
    // incl. the (-1,0)->0 "kept" quirk of the reference
    int cx = (int)((gx + 54.0f) / 0.3f);
    int cy = (int)((gy + 54.0f) / 0.3f);
    int cz = (int)((gz + 10.0f) / 20.0f);

    bool pass = (unsigned)cx < (unsigned)NX_ && (unsigned)cy < (unsigned)NY_
                && cz == 0;
    unsigned mask = __ballot_sync(0xFFFFFFFFu, pass);
    bool live = false;

    unsigned xbase = (((b * D_ + d) * H_) * W_ + w) * (unsigned)C_;   // h = 0

    if (mask != 0u) {
        int src = __ffs(mask) - 1;
        int cx0 = __shfl_sync(0xFFFFFFFFu, cx, src);
        int cy0 = __shfl_sync(0xFFFFFFFFu, cy, src);
        bool uni = __all_sync(0xFFFFFFFFu, !pass || (cx == cx0 && cy == cy0));
        if (uni) {
            live = true;
            if (lane == 0) {
                s_mask[wid] = mask;
                s_q[wid]    = (unsigned)cx0 * NY_ + (unsigned)cy0;
            }
        } else {
            // exact fallback (never expected): per-h scalar scatter now
            if (lane == 0) s_mask[wid] = 0u;
            for (unsigned h = 0; h < H_; h++) {
                if (!((mask >> h) & 1u)) continue;
                int cxh = __shfl_sync(0xFFFFFFFFu, cx, h);
                int cyh = __shfl_sync(0xFFFFFFFFu, cy, h);
                unsigned q = (unsigned)cxh * NY_ + (unsigned)cyh;
                const float* xr = x + xbase + h * (unsigned)(W_ * C_);
                for (unsigned c = lane; c < C_; c += 32)
                    atomicAdd(out + (b * C_ + c) * (unsigned)XY_ + q, xr[c]);
            }
        }
    } else {
        if (lane == 0) s_mask[wid] = 0u;
    }

    // --------------- phase 2: register accumulate -> smem stage -------------
    if (live && lane < C_ / 4) {
        const float* xp = x + xbase + 4u * lane;
        float4 acc = make_float4(0.f, 0.f, 0.f, 0.f);
        #pragma unroll
        for (unsigned h = 0; h < H_; h++) {
            if ((mask >> h) & 1u) {      // warp-uniform: scalar branch
                float4 v = __ldcs(reinterpret_cast<const float4*>(
                    xp + h * (unsigned)(W_ * C_)));
                acc.x += v.x; acc.y += v.y; acc.z += v.z; acc.w += v.w;
            }
        }
        *reinterpret_cast<float4*>(&s_acc[wid][4u * lane]) = acc;
    }
    __syncthreads();

    // --------------- phase 3: channel-major commit across 4 columns ---------
    // idx = tid + k*128 over 320 tasks: cl = idx&3 (column), c = idx>>2.
    // 4 consecutive lanes share c and hit the block's 4 neighboring q's ->
    // ~1-2 sectors per channel instead of 4.
    #pragma unroll
    for (int k = 0; k < 3; k++) {
        unsigned idx = tid + k * 128u;
        if (idx >= WPB_ * C_) break;
        unsigned cl = idx & (WPB_ - 1u);
        unsigned c  = idx / WPB_;
        if (s_mask[cl] != 0u)
            atomicAdd(out + (b * C_ + c) * (unsigned)XY_ + s_q[cl],
                      s_acc[cl][c]);
    }
}

// ---------------- launch ----------------------------------------------------
extern "C" void kernel_launch(void* const* d_in, const int* in_sizes, int n_in,
                              void* d_out, int out_size) {
    const float* x       = (const float*)d_in[0];
    const float* rots    = (const float*)d_in[1];
    const float* trans   = (const float*)d_in[2];
    const float* intrins = (const float*)d_in[3];
    const float* frustum = (const float*)d_in[4];
    float* out = (float*)d_out;

    // 41,472,000 floats = 10,368,000 float4 = 40500 * 256 exactly
    zero_out_kernel<<<40500, 256>>>(reinterpret_cast<float4*>(out));

    // one warp per (b,d,w) column: 41536 warps, 4 per 128-thread block
    scatter_kernel<<<NCOL / WPB_, 128>>>(x, frustum, out, rots, trans, intrins);
}

// round 14
// speedup vs baseline: 1.0447x; 1.0447x over previous
#include <cuda_runtime.h>

// ---------------- problem constants (fixed shapes) ----------------
#define B_    4
#define D_    118
#define H_    32              // == warp size: lane <-> h
#define W_    88
#define C_    80
#define NX_   360
#define NY_   360
#define XY_   (NX_ * NY_)     // 129600
#define NCOLB (D_ * W_)       // 10,384 columns per batch (divisible by 8)
#define NCOL  (B_ * NCOLB)    // 41,536 ray columns

// ---------------- kernel 1: zero all of d_out (poisoned 0xAA) --------------
__global__ void zero_out_kernel(float4* __restrict__ o) {
    unsigned i = blockIdx.x * blockDim.x + threadIdx.x;
    o[i] = make_float4(0.f, 0.f, 0.f, 0.f);   // grid sized exactly: no guard
}

// ---------------- kernel 2: warp-per-column scatter, block-wide commit -----
// Structural fact (validated R5-R13): combine[0][1] == combine[1][1] == 0
// exactly in fp32, so gx,gy are identical across the 32 h's of a (b,d,w)
// column; only the cz==0 test varies with h. Phase 1: each of the 8 warps
// computes its column's mask/voxel (lane == h) with ballot + uniformity
// fallback. Phase 2: accumulate over h with UNCONDITIONAL loads (addresses
// always valid; measured: ~all h's pass in live columns, so conditional
// loads saved no traffic but their control deps blocked ptxas from
// front-batching the LDG.128 stream) and predicated adds (sums bit-exact).
// Phase 3: channel-major commit across the block's 8 adjacent-w columns
// (R12's proven sector collapse).
__global__ void __launch_bounds__(256)
scatter_kernel(const float* __restrict__ x, const float* __restrict__ frustum,
               float* __restrict__ out,
               const float* __restrict__ rots,
               const float* __restrict__ trans,
               const float* __restrict__ intrins) {
    __shared__ float    s_cmb[9];
    __shared__ float    s_tr[3];
    __shared__ float    s_acc[8][C_];
    __shared__ unsigned s_mask[8];
    __shared__ unsigned s_q[8];

    unsigned tid  = threadIdx.x;
    unsigned lane = tid & 31u;                    // lane == h
    unsigned wid  = tid >> 5;
    unsigned col  = blockIdx.x * 8u + wid;        // one column per warp
    unsigned w = col % W_;
    unsigned t = col / W_;
    unsigned d = t % D_;
    unsigned b = t / D_;                          // uniform across the block

    // --- per-block setup: combine = rots[b] @ inv(intrins[b]) (dbl adjugate)
    if (tid == 0) {
        const float* K = intrins + b * 9;
        double a00 = K[0], a01 = K[1], a02 = K[2];
        double a10 = K[3], a11 = K[4], a12 = K[5];
        double a20 = K[6], a21 = K[7], a22 = K[8];
        double det = a00 * (a11 * a22 - a12 * a21)
                   - a01 * (a10 * a22 - a12 * a20)
                   + a02 * (a10 * a21 - a11 * a20);
        double id = 1.0 / det;
        float inv[9];
        inv[0] = (float)(( a11 * a22 - a12 * a21) * id);
        inv[1] = (float)((-(a01 * a22 - a02 * a21)) * id);
        inv[2] = (float)(( a01 * a12 - a02 * a11) * id);
        inv[3] = (float)((-(a10 * a22 - a12 * a20)) * id);
        inv[4] = (float)(( a00 * a22 - a02 * a20) * id);
        inv[5] = (float)((-(a00 * a12 - a02 * a10)) * id);
        inv[6] = (float)(( a10 * a21 - a11 * a20) * id);
        inv[7] = (float)((-(a00 * a21 - a01 * a20)) * id);
        inv[8] = (float)(( a00 * a11 - a01 * a10) * id);
        const float* R = rots + b * 9;
        #pragma unroll
        for (int i = 0; i < 3; i++)
            #pragma unroll
            for (int j = 0; j < 3; j++)
                s_cmb[i * 3 + j] = R[i * 3 + 0] * inv[0 * 3 + j]
                                 + R[i * 3 + 1] * inv[1 * 3 + j]
                                 + R[i * 3 + 2] * inv[2 * 3 + j];
        s_tr[0] = trans[b * 3 + 0];
        s_tr[1] = trans[b * 3 + 1];
        s_tr[2] = trans[b * 3 + 2];
    }
    __syncthreads();

    // --------------- phase 1: mask + voxel for this warp's column -----------
    // frustum (D,H,W,3): [...,0]=u (w only), [...,1]=v (h only), [...,2]=depth
    const float* fr = frustum + ((d * H_ + lane) * W_ + w) * 3u;
    float fu = fr[0];     // uniform across lanes
    float fv = fr[1];     // per-lane (h)
    float fd = fr[2];     // uniform across lanes
    float p0 = fu * fd, p1 = fv * fd, p2 = fd;

    float gx = s_cmb[0] * p0 + s_cmb[1] * p1 + s_cmb[2] * p2 + s_tr[0];
    float gy = s_cmb[3] * p0 + s_cmb[4] * p1 + s_cmb[5] * p2 + s_tr[1];
    float gz = s_cmb[6] * p0 + s_cmb[7] * p1 + s_cmb[8] * p2 + s_tr[2];

    // matches ((geom - BX_LO)/DX).astype(int32): trunc toward zero,
    // incl. the (-1,0)->0 "kept" quirk of the reference
    int cx = (int)((gx + 54.0f) / 0.3f);
    int cy = (int)((gy + 54.0f) / 0.3f);
    int cz = (int)((gz + 10.0f) / 20.0f);

    bool pass = (unsigned)cx < (unsigned)NX_ && (unsigned)cy < (unsigned)NY_
                && cz == 0;
    unsigned mask = __ballot_sync(0xFFFFFFFFu, pass);
    bool live = false;

    unsigned xbase = (((b * D_ + d) * H_) * W_ + w) * (unsigned)C_;   // h = 0

    if (mask != 0u) {
        int src = __ffs(mask) - 1;
        int cx0 = __shfl_sync(0xFFFFFFFFu, cx, src);
        int cy0 = __shfl_sync(0xFFFFFFFFu, cy, src);
        bool uni = __all_sync(0xFFFFFFFFu, !pass || (cx == cx0 && cy == cy0));
        if (uni) {
            live = true;
            if (lane == 0) {
                s_mask[wid] = mask;
                s_q[wid]    = (unsigned)cx0 * NY_ + (unsigned)cy0;
            }
        } else {
            // exact fallback (never expected): per-h scalar scatter now
            if (lane == 0) s_mask[wid] = 0u;
            for (unsigned h = 0; h < H_; h++) {
                if (!((mask >> h) & 1u)) continue;
                int cxh = __shfl_sync(0xFFFFFFFFu, cx, h);
                int cyh = __shfl_sync(0xFFFFFFFFu, cy, h);
                unsigned q = (unsigned)cxh * NY_ + (unsigned)cyh;
                const float* xr = x + xbase + h * (unsigned)(W_ * C_);
                for (unsigned c = lane; c < C_; c += 32)
                    atomicAdd(out + (b * C_ + c) * (unsigned)XY_ + q, xr[c]);
            }
        }
    } else {
        if (lane == 0) s_mask[wid] = 0u;
    }

    // --------------- phase 2: branch-free load stream -> smem stage ---------
    if (live && lane < C_ / 4) {
        const float* xp = x + xbase + 4u * lane;
        float4 acc = make_float4(0.f, 0.f, 0.f, 0.f);
        #pragma unroll
        for (unsigned h = 0; h < H_; h++) {
            // UNCONDITIONAL load: address valid for every h; lets ptxas
            // front-batch the whole LDG.128 stream (no control dependence).
            float4 v = __ldcs(reinterpret_cast<const float4*>(
                xp + h * (unsigned)(W_ * C_)));
            if ((mask >> h) & 1u) {      // predicated add: sums bit-exact
                acc.x += v.x; acc.y += v.y; acc.z += v.z; acc.w += v.w;
            }
        }
        *reinterpret_cast<float4*>(&s_acc[wid][4u * lane]) = acc;
    }
    __syncthreads();

    // --------------- phase 3: channel-major commit across 8 columns ---------
    // idx = tid + k*256 over 640 tasks: cl = idx&7 (column), c = idx>>3.
    // 8 consecutive lanes share c and hit the block's 8 neighboring q's ->
    // 1-2 sectors per channel instead of 8.
    #pragma unroll
    for (int k = 0; k < 3; k++) {
        unsigned idx = tid + k * 256u;
        if (idx >= 8u * C_) break;
        unsigned cl = idx & 7u;
        unsigned c  = idx >> 3;
        if (s_mask[cl] != 0u)
            atomicAdd(out + (b * C_ + c) * (unsigned)XY_ + s_q[cl],
                      s_acc[cl][c]);
    }
}

// ---------------- launch ----------------------------------------------------
extern "C" void kernel_launch(void* const* d_in, const int* in_sizes, int n_in,
                              void* d_out, int out_size) {
    const float* x       = (const float*)d_in[0];
    const float* rots    = (const float*)d_in[1];
    const float* trans   = (const float*)d_in[2];
    const float* intrins = (const float*)d_in[3];
    const float* frustum = (const float*)d_in[4];
    float* out = (float*)d_out;

    // 41,472,000 floats = 10,368,000 float4 = 40500 * 256 exactly
    zero_out_kernel<<<40500, 256>>>(reinterpret_cast<float4*>(out));

    // one warp per (b,d,w) column: 41536 warps, 8 per 256-thread block
    scatter_kernel<<<NCOL / 8, 256>>>(x, frustum, out, rots, trans, intrins);
}

// round 15
// speedup vs baseline: 1.0702x; 1.0244x over previous
#include <cuda_runtime.h>

// ---------------- problem constants (fixed shapes) ----------------
#define B_    4
#define D_    118
#define H_    32              // == warp size: lane <-> h
#define W_    88
#define C_    80
#define NX_   360
#define NY_   360
#define XY_   (NX_ * NY_)     // 129600
#define NCOLB (D_ * W_)       // 10,384 columns per batch (divisible by 8)
#define NCOL  (B_ * NCOLB)    // 41,536 ray columns
#define OUT_N4 ((unsigned)(B_ * C_ * XY_ / 4))   // 10,368,000 float4
#define ZGRID 296             // persistent zero: 2 blocks/SM, all wave-1

// ---------------- kernel 1: persistent zero of d_out + early PDL trigger ---
// All 296 blocks are resident in wave 1, so every block fires the trigger at
// t~0 -> the PDL-attributed scatter launches immediately and its x-read phase
// runs concurrent with this kernel's stores. Correctness does NOT depend on
// the trigger: scatter calls cudaGridDependencySynchronize() (waits for this
// grid's completion) before touching out.
__global__ void __launch_bounds__(256)
zero_out_kernel(float4* __restrict__ o) {
    cudaTriggerProgrammaticLaunchCompletion();
    const float4 z = make_float4(0.f, 0.f, 0.f, 0.f);
    unsigned stride = ZGRID * 256u;
    for (unsigned i = blockIdx.x * 256u + threadIdx.x; i < OUT_N4; i += stride)
        o[i] = z;
}

// ---------------- kernel 2: warp-per-column scatter, block-wide commit -----
// Structural fact (validated R5-R14): combine[0][1] == combine[1][1] == 0
// exactly in fp32, so gx,gy are identical across the 32 h's of a (b,d,w)
// column; only the cz==0 test varies with h. Phase 1: each of the 8 warps
// computes its column's mask/voxel (ballot over lane == h) with a uniformity
// check. Phase 2: branch-free LDG.128 stream + predicated adds (R14 win).
// Then ONE cudaGridDependencySynchronize() — the PDL join with the zero
// kernel — before any out access. Phase 3: channel-major commit across the
// block's 8 adjacent-w columns (R12 sector collapse). The exact per-h
// fallback (never expected) runs after the join too.
__global__ void __launch_bounds__(256)
scatter_kernel(const float* __restrict__ x, const float* __restrict__ frustum,
               float* __restrict__ out,
               const float* __restrict__ rots,
               const float* __restrict__ trans,
               const float* __restrict__ intrins) {
    __shared__ float    s_cmb[9];
    __shared__ float    s_tr[3];
    __shared__ float    s_acc[8][C_];
    __shared__ unsigned s_mask[8];
    __shared__ unsigned s_q[8];

    unsigned tid  = threadIdx.x;
    unsigned lane = tid & 31u;                    // lane == h
    unsigned wid  = tid >> 5;
    unsigned col  = blockIdx.x * 8u + wid;        // one column per warp
    unsigned w = col % W_;
    unsigned t = col / W_;
    unsigned d = t % D_;
    unsigned b = t / D_;                          // uniform across the block

    // --- per-block setup: combine = rots[b] @ inv(intrins[b]) (dbl adjugate)
    if (tid == 0) {
        const float* K = intrins + b * 9;
        double a00 = K[0], a01 = K[1], a02 = K[2];
        double a10 = K[3], a11 = K[4], a12 = K[5];
        double a20 = K[6], a21 = K[7], a22 = K[8];
        double det = a00 * (a11 * a22 - a12 * a21)
                   - a01 * (a10 * a22 - a12 * a20)
                   + a02 * (a10 * a21 - a11 * a20);
        double id = 1.0 / det;
        float inv[9];
        inv[0] = (float)(( a11 * a22 - a12 * a21) * id);
        inv[1] = (float)((-(a01 * a22 - a02 * a21)) * id);
        inv[2] = (float)(( a01 * a12 - a02 * a11) * id);
        inv[3] = (float)((-(a10 * a22 - a12 * a20)) * id);
        inv[4] = (float)(( a00 * a22 - a02 * a20) * id);
        inv[5] = (float)((-(a00 * a12 - a02 * a10)) * id);
        inv[6] = (float)(( a10 * a21 - a11 * a20) * id);
        inv[7] = (float)((-(a00 * a21 - a01 * a20)) * id);
        inv[8] = (float)(( a00 * a11 - a01 * a10) * id);
        const float* R = rots + b * 9;
        #pragma unroll
        for (int i = 0; i < 3; i++)
            #pragma unroll
            for (int j = 0; j < 3; j++)
                s_cmb[i * 3 + j] = R[i * 3 + 0] * inv[0 * 3 + j]
                                 + R[i * 3 + 1] * inv[1 * 3 + j]
                                 + R[i * 3 + 2] * inv[2 * 3 + j];
        s_tr[0] = trans[b * 3 + 0];
        s_tr[1] = trans[b * 3 + 1];
        s_tr[2] = trans[b * 3 + 2];
    }
    __syncthreads();

    // --------------- phase 1: mask + voxel for this warp's column -----------
    // frustum (D,H,W,3): [...,0]=u (w only), [...,1]=v (h only), [...,2]=depth
    const float* fr = frustum + ((d * H_ + lane) * W_ + w) * 3u;
    float fu = fr[0];     // uniform across lanes
    float fv = fr[1];     // per-lane (h)
    float fd = fr[2];     // uniform across lanes
    float p0 = fu * fd, p1 = fv * fd, p2 = fd;

    float gx = s_cmb[0] * p0 + s_cmb[1] * p1 + s_cmb[2] * p2 + s_tr[0];
    float gy = s_cmb[3] * p0 + s_cmb[4] * p1 + s_cmb[5] * p2 + s_tr[1];
    float gz = s_cmb[6] * p0 + s_cmb[7] * p1 + s_cmb[8] * p2 + s_tr[2];

    // matches ((geom - BX_LO)/DX).astype(int32): trunc toward zero,
    // incl. the (-1,0)->0 "kept" quirk of the reference
    int cx = (int)((gx + 54.0f) / 0.3f);
    int cy = (int)((gy + 54.0f) / 0.3f);
    int cz = (int)((gz + 10.0f) / 20.0f);

    bool pass = (unsigned)cx < (unsigned)NX_ && (unsigned)cy < (unsigned)NY_
                && cz == 0;
    unsigned mask = __ballot_sync(0xFFFFFFFFu, pass);
    bool live = false, fb = false;

    unsigned xbase = (((b * D_ + d) * H_) * W_ + w) * (unsigned)C_;   // h = 0

    if (mask != 0u) {
        int src = __ffs(mask) - 1;
        int cx0 = __shfl_sync(0xFFFFFFFFu, cx, src);
        int cy0 = __shfl_sync(0xFFFFFFFFu, cy, src);
        bool uni = __all_sync(0xFFFFFFFFu, !pass || (cx == cx0 && cy == cy0));
        if (uni) {
            live = true;
            if (lane == 0) {
                s_mask[wid] = mask;
                s_q[wid]    = (unsigned)cx0 * NY_ + (unsigned)cy0;
            }
        } else {
            fb = true;                     // defer exact fallback past the join
            if (lane == 0) s_mask[wid] = 0u;
        }
    } else {
        if (lane == 0) s_mask[wid] = 0u;
    }

    // --------------- phase 2: branch-free load stream -> smem stage ---------
    // Runs fully concurrent with the zero kernel (no out access here).
    if (live && lane < C_ / 4) {
        const float* xp = x + xbase + 4u * lane;
        float4 acc = make_float4(0.f, 0.f, 0.f, 0.f);
        #pragma unroll
        for (unsigned h = 0; h < H_; h++) {
            // UNCONDITIONAL load: address valid for every h; keeps the
            // LDG.128 stream free of control deps so ptxas front-batches it.
            float4 v = __ldcs(reinterpret_cast<const float4*>(
                xp + h * (unsigned)(W_ * C_)));
            if ((mask >> h) & 1u) {        // predicated add: sums bit-exact
                acc.x += v.x; acc.y += v.y; acc.z += v.z; acc.w += v.w;
            }
        }
        *reinterpret_cast<float4*>(&s_acc[wid][4u * lane]) = acc;
    }
    __syncthreads();

    // --------------- PDL join: zero kernel must be complete ------------------
    cudaGridDependencySynchronize();

    // --------------- phase 3: channel-major commit across 8 columns ---------
    // idx = tid + k*256 over 640 tasks: cl = idx&7 (column), c = idx>>3.
    // 8 consecutive lanes share c and hit the block's 8 neighboring q's ->
    // 1-2 sectors per channel instead of 8.
    #pragma unroll
    for (int k = 0; k < 3; k++) {
        unsigned idx = tid + k * 256u;
        if (idx >= 8u * C_) break;
        unsigned cl = idx & 7u;
        unsigned c  = idx >> 3;
        if (s_mask[cl] != 0u)
            atomicAdd(out + (b * C_ + c) * (unsigned)XY_ + s_q[cl],
                      s_acc[cl][c]);
    }

    // --------------- exact fallback (never expected), after the join --------
    if (fb) {
        for (unsigned h = 0; h < H_; h++) {
            if (!((mask >> h) & 1u)) continue;
            int cxh = __shfl_sync(0xFFFFFFFFu, cx, h);
            int cyh = __shfl_sync(0xFFFFFFFFu, cy, h);
            unsigned q = (unsigned)cxh * NY_ + (unsigned)cyh;
            const float* xr = x + xbase + h * (unsigned)(W_ * C_);
            for (unsigned c = lane; c < C_; c += 32)
                atomicAdd(out + (b * C_ + c) * (unsigned)XY_ + q, xr[c]);
        }
    }
}

// ---------------- launch ----------------------------------------------------
extern "C" void kernel_launch(void* const* d_in, const int* in_sizes, int n_in,
                              void* d_out, int out_size) {
    const float* x       = (const float*)d_in[0];
    const float* rots    = (const float*)d_in[1];
    const float* trans   = (const float*)d_in[2];
    const float* intrins = (const float*)d_in[3];
    const float* frustum = (const float*)d_in[4];
    float* out = (float*)d_out;

    // persistent zero: 2 blocks/SM, trigger fires at t~0
    zero_out_kernel<<<ZGRID, 256>>>(reinterpret_cast<float4*>(out));

    // scatter with PDL: launches immediately after the zero's trigger; its
    // x-read phase overlaps the zero, the in-kernel join orders the commits.
    cudaLaunchConfig_t cfg = {};
    cfg.gridDim  = dim3(NCOL / 8);
    cfg.blockDim = dim3(256);
    cfg.dynamicSmemBytes = 0;
    cfg.stream = 0;                       // capture stream (legacy default)
    cudaLaunchAttribute attrs[1];
    attrs[0].id = cudaLaunchAttributeProgrammaticStreamSerialization;
    attrs[0].val.programmaticStreamSerializationAllowed = 1;
    cfg.attrs = attrs;
    cfg.numAttrs = 1;
    cudaLaunchKernelEx(&cfg, scatter_kernel,
                       x, frustum, out, rots, trans, intrins);
}